// round 1
// baseline (speedup 1.0000x reference)
#include <cuda_runtime.h>
#include <cstddef>

#define Nn   512
#define IND  256
#define HIDD 256
#define AH   128
#define OUTD 256
#define WELD 262   // IN_DIM + 6

// ---------------- scratch (no allocations allowed) ----------------
__device__ float g_F[Nn * HIDD];       // F[j,h] = We[:,6:] @ app[j] + be
__device__ float g_q[Nn * AH];         // q = app @ Wq^T + bq
__device__ float g_qk[Nn * HIDD];      // qk = (q @ Wk) / sqrt(AH)
__device__ float g_S[Nn * Nn];         // scores -> attention weights (in place)
__device__ float g_wp[4 * Nn * HIDD];  // per-j-chunk partials of w
__device__ float g_w[Nn * HIDD];       // w[i] = sum_j A[i,j] E[i,j]
__device__ float g_agg[Nn * HIDD];     // agg = w @ Wv^T + bv

// ---------------- generic small fp32 GEMM: C = act(alpha*A@op(B) + bias [+C]) ----
// TRANSB: B stored [N,K] (use B^T), else [K,N].
// Tiles 32x32, K-step 32, 256 threads, 2x2 micro-tile. All dims multiples of 32.
template <bool TRANSB, bool ACCUM, bool RELU>
__global__ __launch_bounds__(256) void gemm_k(
    const float* __restrict__ A, int lda,
    const float* __restrict__ B, int ldb,
    const float* __restrict__ bias,
    float* __restrict__ C, int ldc,
    int K, float alpha)
{
    __shared__ float As[32][34];
    __shared__ float Bs[32][34];
    const int t = threadIdx.x;
    const int tx = t & 15, ty = t >> 4;
    const int mb = blockIdx.y * 32, nb = blockIdx.x * 32;
    float a00 = 0.f, a01 = 0.f, a10 = 0.f, a11 = 0.f;

    for (int k0 = 0; k0 < K; k0 += 32) {
#pragma unroll
        for (int r = 0; r < 4; r++) {
            int idx = t + r * 256;
            int p = idx >> 5, s = idx & 31;
            As[s][p] = A[(size_t)(mb + p) * lda + (k0 + s)];
            if (TRANSB)
                Bs[s][p] = B[(size_t)(nb + p) * ldb + (k0 + s)];
            else
                Bs[p][s] = B[(size_t)(k0 + p) * ldb + (nb + s)];
        }
        __syncthreads();
#pragma unroll
        for (int kk = 0; kk < 32; kk++) {
            float2 av = *(const float2*)&As[kk][ty * 2];
            float2 bv = *(const float2*)&Bs[kk][tx * 2];
            a00 = fmaf(av.x, bv.x, a00);
            a01 = fmaf(av.x, bv.y, a01);
            a10 = fmaf(av.y, bv.x, a10);
            a11 = fmaf(av.y, bv.y, a11);
        }
        __syncthreads();
    }

    int m = mb + ty * 2, n = nb + tx * 2;
    float b0 = bias ? bias[n] : 0.f;
    float b1 = bias ? bias[n + 1] : 0.f;
    float v00 = fmaf(alpha, a00, b0), v01 = fmaf(alpha, a01, b1);
    float v10 = fmaf(alpha, a10, b0), v11 = fmaf(alpha, a11, b1);
    if (ACCUM) {
        v00 += C[(size_t)m * ldc + n];
        v01 += C[(size_t)m * ldc + n + 1];
        v10 += C[(size_t)(m + 1) * ldc + n];
        v11 += C[(size_t)(m + 1) * ldc + n + 1];
    }
    if (RELU) {
        v00 = fmaxf(v00, 0.f); v01 = fmaxf(v01, 0.f);
        v10 = fmaxf(v10, 0.f); v11 = fmaxf(v11, 0.f);
    }
    C[(size_t)m * ldc + n]           = v00;
    C[(size_t)m * ldc + n + 1]       = v01;
    C[(size_t)(m + 1) * ldc + n]     = v10;
    C[(size_t)(m + 1) * ldc + n + 1] = v11;
}

// ---------------- pass A: S[i,j] = qk[i] . ReLU(edges[i,j]·We_e + F[j]) ----------
// 16x16 (i,j) tile per block; thread = one (i,j); loop over h with smem-resident
// transposed qk/F tiles (broadcast / conflict-free LDS).
__global__ __launch_bounds__(256) void passA_k(
    const float* __restrict__ edges,
    const float* __restrict__ We,
    const float* __restrict__ Fm,
    const float* __restrict__ qk,
    float* __restrict__ S)
{
    __shared__ float qk_s[HIDD][17];
    __shared__ float F_s[HIDD][17];
    __shared__ float We_s[HIDD * 8];

    const int t = threadIdx.x;
    const int jj = t & 15, ii = t >> 4;
    const int i0 = blockIdx.y * 16, j0 = blockIdx.x * 16;

    {   // edge part of We: one row per thread, padded to 8 for float4 reads
        const float* wr = We + (size_t)t * WELD;
#pragma unroll
        for (int c = 0; c < 6; c++) We_s[t * 8 + c] = wr[c];
        We_s[t * 8 + 6] = 0.f;
        We_s[t * 8 + 7] = 0.f;
    }
#pragma unroll
    for (int r = 0; r < 16; r++) {
        int idx = t + r * 256;
        int il = idx >> 8, h = idx & 255;
        qk_s[h][il] = qk[(size_t)(i0 + il) * HIDD + h];
        F_s[h][il]  = Fm[(size_t)(j0 + il) * HIDD + h];
    }

    const int i = i0 + ii, j = j0 + jj;
    const float* ep = edges + ((size_t)i * Nn + j) * 6;
    const float e0 = ep[0], e1 = ep[1], e2 = ep[2];
    const float e3 = ep[3], e4 = ep[4], e5 = ep[5];
    __syncthreads();

    float acc = 0.f;
#pragma unroll 4
    for (int h = 0; h < HIDD; h++) {
        float4 w0 = *(const float4*)&We_s[h * 8];
        float2 w1 = *(const float2*)&We_s[h * 8 + 4];
        float g = F_s[h][jj];
        g = fmaf(e0, w0.x, g);
        g = fmaf(e1, w0.y, g);
        g = fmaf(e2, w0.z, g);
        g = fmaf(e3, w0.w, g);
        g = fmaf(e4, w1.x, g);
        g = fmaf(e5, w1.y, g);
        g = fmaxf(g, 0.f);
        acc = fmaf(qk_s[h][ii], g, acc);
    }
    S[(size_t)i * Nn + j] = acc;   // scale already folded into qk
}

// ---------------- softmax over each row (diag masked), in place ----------------
__global__ __launch_bounds__(256) void softmax_k(float* __restrict__ S)
{
    const int i = blockIdx.x, t = threadIdx.x;
    float v0 = S[(size_t)i * Nn + t];
    float v1 = S[(size_t)i * Nn + 256 + t];
    if (t == i)       v0 = -1e30f;
    if (t + 256 == i) v1 = -1e30f;

    __shared__ float red[16];
    float m = fmaxf(v0, v1);
#pragma unroll
    for (int o = 16; o; o >>= 1) m = fmaxf(m, __shfl_xor_sync(0xffffffffu, m, o));
    if ((t & 31) == 0) red[t >> 5] = m;
    __syncthreads();
    m = red[0];
#pragma unroll
    for (int k = 1; k < 8; k++) m = fmaxf(m, red[k]);

    float p0 = __expf(v0 - m), p1 = __expf(v1 - m);
    float s = p0 + p1;
#pragma unroll
    for (int o = 16; o; o >>= 1) s += __shfl_xor_sync(0xffffffffu, s, o);
    if ((t & 31) == 0) red[8 + (t >> 5)] = s;
    __syncthreads();
    s = 0.f;
#pragma unroll
    for (int k = 0; k < 8; k++) s += red[8 + k];
    float inv = 1.f / s;
    S[(size_t)i * Nn + t]       = p0 * inv;
    S[(size_t)i * Nn + 256 + t] = p1 * inv;
}

// ---------------- pass B: w[i,h] = sum_j A[i,j] * ReLU(edges[i,j]·We_e + F[j,h]) --
// Block: 8 i-rows x 128-j chunk; thread owns h = tid; partials per chunk
// (deterministic, no float atomics).
__global__ __launch_bounds__(256) void passB_k(
    const float* __restrict__ edges,
    const float* __restrict__ We,
    const float* __restrict__ Fm,
    const float* __restrict__ A,
    float* __restrict__ wp)
{
    __shared__ float F_s[32][256];
    __shared__ float ea_s[32][8][8];   // [jj][ii][0..5]=edges, [6]=A, [7]=pad

    const int t = threadIdx.x;
    const int h = t;
    const int i0 = blockIdx.y * 8;
    const int jbase = blockIdx.x * 128;

    const float* wr = We + (size_t)h * WELD;
    const float we0 = wr[0], we1 = wr[1], we2 = wr[2];
    const float we3 = wr[3], we4 = wr[4], we5 = wr[5];

    float wacc[8];
#pragma unroll
    for (int k = 0; k < 8; k++) wacc[k] = 0.f;

    for (int sub = 0; sub < 4; sub++) {
        const int j0 = jbase + sub * 32;
#pragma unroll
        for (int r = 0; r < 8; r++) {            // stage F tile (float4, coalesced)
            int idx = t + r * 256;
            int jj = idx >> 6, hq = idx & 63;
            *((float4*)&F_s[jj][0] + hq) =
                *((const float4*)(Fm + (size_t)(j0 + jj) * HIDD) + hq);
        }
        {                                        // stage edges + A
            int jj = t >> 3, ii = t & 7;
            const float* ep = edges + ((size_t)(i0 + ii) * Nn + (j0 + jj)) * 6;
            float2 x01 = *(const float2*)ep;
            float2 x23 = *(const float2*)(ep + 2);
            float2 x45 = *(const float2*)(ep + 4);
            float av = A[(size_t)(i0 + ii) * Nn + (j0 + jj)];
            float* d = &ea_s[jj][ii][0];
            d[0] = x01.x; d[1] = x01.y; d[2] = x23.x;
            d[3] = x23.y; d[4] = x45.x; d[5] = x45.y;
            d[6] = av;    d[7] = 0.f;
        }
        __syncthreads();

#pragma unroll 2
        for (int jj = 0; jj < 32; jj++) {
            float f = F_s[jj][h];
#pragma unroll
            for (int ii = 0; ii < 8; ii++) {
                float4 v0 = *(const float4*)&ea_s[jj][ii][0];
                float4 v1 = *(const float4*)&ea_s[jj][ii][4];
                float g = fmaf(v0.x, we0, f);
                g = fmaf(v0.y, we1, g);
                g = fmaf(v0.z, we2, g);
                g = fmaf(v0.w, we3, g);
                g = fmaf(v1.x, we4, g);
                g = fmaf(v1.y, we5, g);
                g = fmaxf(g, 0.f);
                wacc[ii] = fmaf(v1.z, g, wacc[ii]);
            }
        }
        __syncthreads();
    }

    float* dst = wp + (size_t)blockIdx.x * (Nn * HIDD);
#pragma unroll
    for (int ii = 0; ii < 8; ii++)
        dst[(size_t)(i0 + ii) * HIDD + h] = wacc[ii];
}

// ---------------- reduce the 4 j-chunk partials ----------------
__global__ __launch_bounds__(256) void reduce_w_k(const float* __restrict__ wp,
                                                  float* __restrict__ w)
{
    int idx = blockIdx.x * 256 + threadIdx.x;
    w[idx] = wp[idx] + wp[Nn * HIDD + idx] + wp[2 * Nn * HIDD + idx] +
             wp[3 * Nn * HIDD + idx];
}

// ---------------- launch ----------------
extern "C" void kernel_launch(void* const* d_in, const int* in_sizes, int n_in,
                              void* d_out, int out_size)
{
    const float* app   = (const float*)d_in[0];
    const float* edges = (const float*)d_in[1];
    const float* We    = (const float*)d_in[2];
    const float* be    = (const float*)d_in[3];
    const float* Wq    = (const float*)d_in[4];
    const float* bq    = (const float*)d_in[5];
    const float* Wk    = (const float*)d_in[6];
    // d_in[7] = bk: constant shift per row -> cancels in softmax, unused
    const float* Wv    = (const float*)d_in[8];
    const float* bv    = (const float*)d_in[9];
    const float* Wo    = (const float*)d_in[10];
    const float* bo    = (const float*)d_in[11];
    float* out = (float*)d_out;

    float *F, *q, *qk, *S, *wp, *w, *agg;
    cudaGetSymbolAddress((void**)&F,   g_F);
    cudaGetSymbolAddress((void**)&q,   g_q);
    cudaGetSymbolAddress((void**)&qk,  g_qk);
    cudaGetSymbolAddress((void**)&S,   g_S);
    cudaGetSymbolAddress((void**)&wp,  g_wp);
    cudaGetSymbolAddress((void**)&w,   g_w);
    cudaGetSymbolAddress((void**)&agg, g_agg);

    // F = app @ We[:,6:]^T + be         [512,256]
    gemm_k<true, false, false><<<dim3(HIDD / 32, Nn / 32), 256>>>(
        app, IND, We + 6, WELD, be, F, HIDD, IND, 1.f);
    // q = app @ Wq^T + bq               [512,128]
    gemm_k<true, false, false><<<dim3(AH / 32, Nn / 32), 256>>>(
        app, IND, Wq, IND, bq, q, AH, IND, 1.f);
    // qk = (q @ Wk) / sqrt(128)         [512,256]
    gemm_k<false, false, false><<<dim3(HIDD / 32, Nn / 32), 256>>>(
        q, AH, Wk, HIDD, nullptr, qk, HIDD, AH, 0.08838834764831845f);

    passA_k<<<dim3(Nn / 16, Nn / 16), 256>>>(edges, We, F, qk, S);
    softmax_k<<<Nn, 256>>>(S);
    passB_k<<<dim3(4, Nn / 8), 256>>>(edges, We, F, S, wp);
    reduce_w_k<<<Nn * HIDD / 256, 256>>>(wp, w);

    // agg = w @ Wv^T + bv               [512,256]
    gemm_k<true, false, false><<<dim3(HIDD / 32, Nn / 32), 256>>>(
        w, HIDD, Wv, HIDD, bv, agg, HIDD, HIDD, 1.f);
    // out = app @ Wo[:, :256]^T
    gemm_k<true, false, false><<<dim3(OUTD / 32, Nn / 32), 256>>>(
        app, IND, Wo, IND + HIDD, nullptr, out, OUTD, IND, 1.f);
    // out = ReLU(out + agg @ Wo[:, 256:]^T + bo)
    gemm_k<true, true, true><<<dim3(OUTD / 32, Nn / 32), 256>>>(
        agg, HIDD, Wo + IND, IND + HIDD, bo, out, OUTD, HIDD, 1.f);
}

// round 2
// speedup vs baseline: 1.2777x; 1.2777x over previous
#include <cuda_runtime.h>
#include <cstddef>

typedef unsigned long long ull;

#define Nn   512
#define IND  256
#define HIDD 256
#define AH   128
#define OUTD 256
#define WELD 262   // IN_DIM + 6

// ---------------- scratch ----------------
__device__ float g_F[Nn * HIDD];
__device__ float g_q[Nn * AH];
__device__ float g_qk[Nn * HIDD];
__device__ float g_S[Nn * Nn];
__device__ float g_wp[4 * Nn * HIDD];
__device__ float g_w[Nn * HIDD];
__device__ float g_agg[Nn * HIDD];

// ---------------- f32x2 helpers ----------------
__device__ __forceinline__ ull pack2(float lo, float hi) {
    ull r; asm("mov.b64 %0,{%1,%2};" : "=l"(r) : "f"(lo), "f"(hi)); return r;
}
__device__ __forceinline__ float2 unp2(ull x) {
    float2 f; asm("mov.b64 {%0,%1},%2;" : "=f"(f.x), "=f"(f.y) : "l"(x)); return f;
}
__device__ __forceinline__ ull fma2(ull a, ull b, ull c) {
    ull d; asm("fma.rn.f32x2 %0,%1,%2,%3;" : "=l"(d) : "l"(a), "l"(b), "l"(c)); return d;
}
__device__ __forceinline__ ull relu2(ull x) {
    ull r;
    asm("{.reg .f32 lo,hi;\n\t"
        "mov.b64 {lo,hi},%1;\n\t"
        "max.f32 lo,lo,0f00000000;\n\t"
        "max.f32 hi,hi,0f00000000;\n\t"
        "mov.b64 %0,{lo,hi};}" : "=l"(r) : "l"(x));
    return r;
}

// ---------------- small fp32 GEMM ----------------
template <bool TRANSB, bool ACCUM, bool RELU>
__global__ __launch_bounds__(256) void gemm_k(
    const float* __restrict__ A, int lda,
    const float* __restrict__ B, int ldb,
    const float* __restrict__ bias,
    float* __restrict__ C, int ldc,
    int K, float alpha)
{
    __shared__ float As[32][34];
    __shared__ float Bs[32][34];
    const int t = threadIdx.x;
    const int tx = t & 15, ty = t >> 4;
    const int mb = blockIdx.y * 32, nb = blockIdx.x * 32;
    float a00 = 0.f, a01 = 0.f, a10 = 0.f, a11 = 0.f;

    for (int k0 = 0; k0 < K; k0 += 32) {
#pragma unroll
        for (int r = 0; r < 4; r++) {
            int idx = t + r * 256;
            int p = idx >> 5, s = idx & 31;
            As[s][p] = A[(size_t)(mb + p) * lda + (k0 + s)];
            if (TRANSB)
                Bs[s][p] = B[(size_t)(nb + p) * ldb + (k0 + s)];
            else
                Bs[p][s] = B[(size_t)(k0 + p) * ldb + (nb + s)];
        }
        __syncthreads();
#pragma unroll
        for (int kk = 0; kk < 32; kk++) {
            float2 av = *(const float2*)&As[kk][ty * 2];
            float2 bv = *(const float2*)&Bs[kk][tx * 2];
            a00 = fmaf(av.x, bv.x, a00);
            a01 = fmaf(av.x, bv.y, a01);
            a10 = fmaf(av.y, bv.x, a10);
            a11 = fmaf(av.y, bv.y, a11);
        }
        __syncthreads();
    }

    int m = mb + ty * 2, n = nb + tx * 2;
    float b0 = bias ? bias[n] : 0.f;
    float b1 = bias ? bias[n + 1] : 0.f;
    float v00 = fmaf(alpha, a00, b0), v01 = fmaf(alpha, a01, b1);
    float v10 = fmaf(alpha, a10, b0), v11 = fmaf(alpha, a11, b1);
    if (ACCUM) {
        v00 += C[(size_t)m * ldc + n];
        v01 += C[(size_t)m * ldc + n + 1];
        v10 += C[(size_t)(m + 1) * ldc + n];
        v11 += C[(size_t)(m + 1) * ldc + n + 1];
    }
    if (RELU) {
        v00 = fmaxf(v00, 0.f); v01 = fmaxf(v01, 0.f);
        v10 = fmaxf(v10, 0.f); v11 = fmaxf(v11, 0.f);
    }
    C[(size_t)m * ldc + n]           = v00;
    C[(size_t)m * ldc + n + 1]       = v01;
    C[(size_t)(m + 1) * ldc + n]     = v10;
    C[(size_t)(m + 1) * ldc + n + 1] = v11;
}

// ---------------- pass A ----------------
#define PA_STR 258
#define PA_SMEM ((2048 + 2 * 32 * PA_STR) * 4)

__global__ __launch_bounds__(256) void passA_k(
    const float* __restrict__ edges,
    const float* __restrict__ We,
    const float* __restrict__ Fm,
    const float* __restrict__ qkm,
    float* __restrict__ S)
{
    extern __shared__ float sm[];
    float* WeP = sm;                    // [128][16]
    float* qs  = sm + 2048;             // [32][258]
    float* fs  = qs + 32 * PA_STR;      // [32][258]

    const int t = threadIdx.x;
    const int tx = t & 15, ty = t >> 4;
    const int i0 = blockIdx.y * 32, j0 = blockIdx.x * 32;

#pragma unroll
    for (int r = 0; r < 3; r++) {
        int idx = t + r * 256;
        int hp = idx / 6, c = idx - hp * 6;
        WeP[hp * 16 + 2 * c]     = We[(size_t)(2 * hp) * WELD + c];
        WeP[hp * 16 + 2 * c + 1] = We[(size_t)(2 * hp + 1) * WELD + c];
    }
#pragma unroll
    for (int r = 0; r < 8; r++) {
        int idx = t + r * 256;
        int il = idx >> 6, hq = (idx & 63) << 2;
        float4 a = *(const float4*)(qkm + (size_t)(i0 + il) * HIDD + hq);
        float4 b = *(const float4*)(Fm  + (size_t)(j0 + il) * HIDD + hq);
        float* qd = qs + il * PA_STR + hq;
        qd[0] = a.x; qd[1] = a.y; qd[2] = a.z; qd[3] = a.w;
        float* fd = fs + il * PA_STR + hq;
        fd[0] = b.x; fd[1] = b.y; fd[2] = b.z; fd[3] = b.w;
    }

    const int ia0 = i0 + ty, ia1 = i0 + ty + 16;
    const int ja0 = j0 + tx, ja1 = j0 + tx + 16;
    ull e[2][2][6];
#pragma unroll
    for (int a = 0; a < 2; a++)
#pragma unroll
        for (int b = 0; b < 2; b++) {
            int i = a ? ia1 : ia0, j = b ? ja1 : ja0;
            const float* ep = edges + ((size_t)i * Nn + j) * 6;
            float2 x0 = *(const float2*)ep;
            float2 x1 = *(const float2*)(ep + 2);
            float2 x2 = *(const float2*)(ep + 4);
            e[a][b][0] = pack2(x0.x, x0.x); e[a][b][1] = pack2(x0.y, x0.y);
            e[a][b][2] = pack2(x1.x, x1.x); e[a][b][3] = pack2(x1.y, x1.y);
            e[a][b][4] = pack2(x2.x, x2.x); e[a][b][5] = pack2(x2.y, x2.y);
        }
    __syncthreads();

    ull z = pack2(0.f, 0.f);
    ull acc[2][2] = {{z, z}, {z, z}};
    const float* qr0 = qs + ty * PA_STR;
    const float* qr1 = qs + (ty + 16) * PA_STR;
    const float* fr0 = fs + tx * PA_STR;
    const float* fr1 = fs + (tx + 16) * PA_STR;

#pragma unroll 2
    for (int hp = 0; hp < 128; hp++) {
        const ulonglong2* wv = (const ulonglong2*)(WeP + hp * 16);
        ulonglong2 wA = wv[0], wB = wv[1], wC = wv[2];
        ull q0 = *(const ull*)(qr0 + 2 * hp);
        ull q1 = *(const ull*)(qr1 + 2 * hp);
        ull f0 = *(const ull*)(fr0 + 2 * hp);
        ull f1 = *(const ull*)(fr1 + 2 * hp);
#pragma unroll
        for (int a = 0; a < 2; a++) {
            ull qa = a ? q1 : q0;
#pragma unroll
            for (int b = 0; b < 2; b++) {
                ull g = b ? f1 : f0;
                g = fma2(e[a][b][0], wA.x, g);
                g = fma2(e[a][b][1], wA.y, g);
                g = fma2(e[a][b][2], wB.x, g);
                g = fma2(e[a][b][3], wB.y, g);
                g = fma2(e[a][b][4], wC.x, g);
                g = fma2(e[a][b][5], wC.y, g);
                g = relu2(g);
                acc[a][b] = fma2(qa, g, acc[a][b]);
            }
        }
    }
    {
        float2 v;
        v = unp2(acc[0][0]); S[(size_t)ia0 * Nn + ja0] = v.x + v.y;
        v = unp2(acc[0][1]); S[(size_t)ia0 * Nn + ja1] = v.x + v.y;
        v = unp2(acc[1][0]); S[(size_t)ia1 * Nn + ja0] = v.x + v.y;
        v = unp2(acc[1][1]); S[(size_t)ia1 * Nn + ja1] = v.x + v.y;
    }
}

// ---------------- softmax ----------------
__global__ __launch_bounds__(256) void softmax_k(float* __restrict__ S)
{
    const int i = blockIdx.x, t = threadIdx.x;
    float v0 = S[(size_t)i * Nn + t];
    float v1 = S[(size_t)i * Nn + 256 + t];
    if (t == i)       v0 = -1e30f;
    if (t + 256 == i) v1 = -1e30f;

    __shared__ float red[16];
    float m = fmaxf(v0, v1);
#pragma unroll
    for (int o = 16; o; o >>= 1) m = fmaxf(m, __shfl_xor_sync(0xffffffffu, m, o));
    if ((t & 31) == 0) red[t >> 5] = m;
    __syncthreads();
    m = red[0];
#pragma unroll
    for (int k = 1; k < 8; k++) m = fmaxf(m, red[k]);

    float p0 = __expf(v0 - m), p1 = __expf(v1 - m);
    float s = p0 + p1;
#pragma unroll
    for (int o = 16; o; o >>= 1) s += __shfl_xor_sync(0xffffffffu, s, o);
    if ((t & 31) == 0) red[8 + (t >> 5)] = s;
    __syncthreads();
    s = 0.f;
#pragma unroll
    for (int k = 0; k < 8; k++) s += red[8 + k];
    float inv = 1.f / s;
    S[(size_t)i * Nn + t]       = p0 * inv;
    S[(size_t)i * Nn + 256 + t] = p1 * inv;
}

// ---------------- pass B ----------------
#define PB_FSTR 258
__global__ __launch_bounds__(256) void passB_k(
    const float* __restrict__ edges,
    const float* __restrict__ We,
    const float* __restrict__ Fm,
    const float* __restrict__ A,
    float* __restrict__ wp)
{
    __shared__ __align__(16) float Fd[32 * PB_FSTR];
    __shared__ __align__(16) float EAe[32 * 4 * 12];
    __shared__ __align__(16) ull   Aa[32 * 4];

    const int t = threadIdx.x;
    const int hp = t & 127;
    const int grp = t >> 7;
    const int i0 = blockIdx.y * 8;
    const int jb = blockIdx.x * 128;

    ull Wr0[6], Wr1[6];
#pragma unroll
    for (int c = 0; c < 6; c++) {
        float w0 = We[(size_t)(2 * hp) * WELD + c];
        float w1 = We[(size_t)(2 * hp + 1) * WELD + c];
        Wr0[c] = pack2(w0, w0);
        Wr1[c] = pack2(w1, w1);
    }

    ull z = pack2(0.f, 0.f);
    ull acc[2][2] = {{z, z}, {z, z}};

    for (int s = 0; s < 4; s++) {
        const int j0 = jb + s * 32;
#pragma unroll
        for (int r = 0; r < 8; r++) {
            int idx = t + r * 256;
            int jj = idx >> 6, hq = (idx & 63) << 2;
            float4 b = *(const float4*)(Fm + (size_t)(j0 + jj) * HIDD + hq);
            float* fd = Fd + jj * PB_FSTR + hq;
            fd[0] = b.x; fd[1] = b.y; fd[2] = b.z; fd[3] = b.w;
        }
        {
            int jj = t & 31, ii = t >> 5;
            const float* ep = edges + ((size_t)(i0 + ii) * Nn + (j0 + jj)) * 6;
            float2 x0 = *(const float2*)ep;
            float2 x1 = *(const float2*)(ep + 2);
            float2 x2 = *(const float2*)(ep + 4);
            int ip = ii >> 1, hf = ii & 1;
            float* d = EAe + (jj * 4 + ip) * 12;
            d[0 + hf] = x0.x; d[2 + hf] = x0.y; d[4 + hf] = x1.x;
            d[6 + hf] = x1.y; d[8 + hf] = x2.x; d[10 + hf] = x2.y;
            ((float*)Aa)[(jj * 4 + ip) * 2 + hf] =
                A[(size_t)(i0 + ii) * Nn + (j0 + jj)];
        }
        __syncthreads();

#pragma unroll 1
        for (int jj = 0; jj < 32; jj++) {
            ull f2 = *(const ull*)(Fd + jj * PB_FSTR + 2 * hp);
            float2 fv = unp2(f2);
            ull fr0 = pack2(fv.x, fv.x);
            ull fr1 = pack2(fv.y, fv.y);
#pragma unroll
            for (int pl = 0; pl < 2; pl++) {
                int ip = grp * 2 + pl;
                const ulonglong2* ev = (const ulonglong2*)(EAe + (jj * 4 + ip) * 12);
                ulonglong2 eA = ev[0], eB = ev[1], eC = ev[2];
                ull a2 = Aa[jj * 4 + ip];
                ull g = fma2(eA.x, Wr0[0], fr0);
                g = fma2(eA.y, Wr0[1], g);
                g = fma2(eB.x, Wr0[2], g);
                g = fma2(eB.y, Wr0[3], g);
                g = fma2(eC.x, Wr0[4], g);
                g = fma2(eC.y, Wr0[5], g);
                g = relu2(g);
                acc[pl][0] = fma2(a2, g, acc[pl][0]);
                ull h = fma2(eA.x, Wr1[0], fr1);
                h = fma2(eA.y, Wr1[1], h);
                h = fma2(eB.x, Wr1[2], h);
                h = fma2(eB.y, Wr1[3], h);
                h = fma2(eC.x, Wr1[4], h);
                h = fma2(eC.y, Wr1[5], h);
                h = relu2(h);
                acc[pl][1] = fma2(a2, h, acc[pl][1]);
            }
        }
        __syncthreads();
    }

    float* dst = wp + (size_t)blockIdx.x * (Nn * HIDD);
#pragma unroll
    for (int pl = 0; pl < 2; pl++) {
        int ie = i0 + (grp * 2 + pl) * 2;
        float2 v0 = unp2(acc[pl][0]);
        float2 v1 = unp2(acc[pl][1]);
        dst[(size_t)ie * HIDD + 2 * hp]           = v0.x;
        dst[(size_t)(ie + 1) * HIDD + 2 * hp]     = v0.y;
        dst[(size_t)ie * HIDD + 2 * hp + 1]       = v1.x;
        dst[(size_t)(ie + 1) * HIDD + 2 * hp + 1] = v1.y;
    }
}

// ---------------- reduce partials ----------------
__global__ __launch_bounds__(256) void reduce_w_k(const float* __restrict__ wp,
                                                  float* __restrict__ w)
{
    int idx = blockIdx.x * 256 + threadIdx.x;
    w[idx] = wp[idx] + wp[Nn * HIDD + idx] + wp[2 * Nn * HIDD + idx] +
             wp[3 * Nn * HIDD + idx];
}

// ---------------- launch ----------------
extern "C" void kernel_launch(void* const* d_in, const int* in_sizes, int n_in,
                              void* d_out, int out_size)
{
    const float* app   = (const float*)d_in[0];
    const float* edges = (const float*)d_in[1];
    const float* We    = (const float*)d_in[2];
    const float* be    = (const float*)d_in[3];
    const float* Wq    = (const float*)d_in[4];
    const float* bq    = (const float*)d_in[5];
    const float* Wk    = (const float*)d_in[6];
    // d_in[7] = bk: per-row constant in S -> cancels in softmax
    const float* Wv    = (const float*)d_in[8];
    const float* bv    = (const float*)d_in[9];
    const float* Wo    = (const float*)d_in[10];
    const float* bo    = (const float*)d_in[11];
    float* out = (float*)d_out;

    float *F, *q, *qk, *S, *wp, *w, *agg;
    cudaGetSymbolAddress((void**)&F,   g_F);
    cudaGetSymbolAddress((void**)&q,   g_q);
    cudaGetSymbolAddress((void**)&qk,  g_qk);
    cudaGetSymbolAddress((void**)&S,   g_S);
    cudaGetSymbolAddress((void**)&wp,  g_wp);
    cudaGetSymbolAddress((void**)&w,   g_w);
    cudaGetSymbolAddress((void**)&agg, g_agg);

    cudaFuncSetAttribute(passA_k, cudaFuncAttributeMaxDynamicSharedMemorySize,
                         PA_SMEM);

    gemm_k<true, false, false><<<dim3(HIDD / 32, Nn / 32), 256>>>(
        app, IND, We + 6, WELD, be, F, HIDD, IND, 1.f);
    gemm_k<true, false, false><<<dim3(AH / 32, Nn / 32), 256>>>(
        app, IND, Wq, IND, bq, q, AH, IND, 1.f);
    gemm_k<false, false, false><<<dim3(HIDD / 32, Nn / 32), 256>>>(
        q, AH, Wk, HIDD, nullptr, qk, HIDD, AH, 0.08838834764831845f);

    passA_k<<<dim3(Nn / 32, Nn / 32), 256, PA_SMEM>>>(edges, We, F, qk, S);
    softmax_k<<<Nn, 256>>>(S);
    passB_k<<<dim3(4, Nn / 8), 256>>>(edges, We, F, S, wp);
    reduce_w_k<<<Nn * HIDD / 256, 256>>>(wp, w);

    gemm_k<true, false, false><<<dim3(HIDD / 32, Nn / 32), 256>>>(
        w, HIDD, Wv, HIDD, bv, agg, HIDD, HIDD, 1.f);
    gemm_k<true, false, false><<<dim3(OUTD / 32, Nn / 32), 256>>>(
        app, IND, Wo, IND + HIDD, nullptr, out, OUTD, IND, 1.f);
    gemm_k<true, true, true><<<dim3(OUTD / 32, Nn / 32), 256>>>(
        agg, HIDD, Wo + IND, IND + HIDD, bo, out, OUTD, HIDD, 1.f);
}